// round 2
// baseline (speedup 1.0000x reference)
#include <cuda_runtime.h>
#include <math.h>

#define DD 32
#define NMAX 100000
#define EMAX 800000

__device__ float  g_hA[NMAX * DD];
__device__ float  g_hB[NMAX * DD];
__device__ float4 g_attr[EMAX];
__device__ float  g_rad[3 * EMAX];
__device__ int    g_deg[NMAX];
__device__ int    g_off[NMAX + 1];
__device__ int    g_cursor[NMAX];
__device__ int    g_perm[EMAX];

#define SQRT3F 1.7320508075688772f
#define SMOOTH_CF 8.4335730691f
#define COMB_NORM 0.022821773229382f

__global__ void pre_kernel(const float* __restrict__ pos,
                           const int*   __restrict__ esrc,
                           const int*   __restrict__ edst,
                           const float* __restrict__ W1,
                           const float* __restrict__ W2,
                           int E)
{
    __shared__ float W1s[3 * 10 * 65 + 32];
    __shared__ float W2s[3 * 64];
    for (int i = threadIdx.x; i < 1920; i += blockDim.x) {
        int l = i / 640, r = i % 640, j = r / 64, h = r % 64;
        W1s[l * 650 + j * 65 + h] = W1[i];
    }
    for (int i = threadIdx.x; i < 192; i += blockDim.x) W2s[i] = W2[i];
    __syncthreads();

    int e = blockIdx.x * blockDim.x + threadIdx.x;
    if (e >= E) return;
    int s = esrc[e], d = edst[e];
    float vx = pos[s * 3 + 0] - pos[d * 3 + 0];
    float vy = pos[s * 3 + 1] - pos[d * 3 + 1];
    float vz = pos[s * 3 + 2] - pos[d * 3 + 2];
    float len = sqrtf(vx * vx + vy * vy + vz * vz);
    float inv = __fdividef(SQRT3F, len + 1e-9f);
    g_attr[e] = make_float4(vy * inv, vz * inv, vx * inv, len);

    if (!(len > 0.0f && len < 5.0f)) return;
    atomicAdd(&g_deg[d], 1);

    float t  = len * 2.2f;
    int   j1 = (int)t;
    float d0 = t - (float)j1;
    float d1 = d0 - 1.0f;
    float ej0 = SMOOTH_CF * __expf(-(__fdividef(1.f, 1.f + d0) + __fdividef(1.f, 1.f - d0)));
    float ej1 = SMOOTH_CF * __expf(-(__fdividef(1.f, 1.f + d1) + __fdividef(1.f, 1.f - d1)));
    int j0 = j1 - 1;
    if (j0 < 0) ej0 = 0.0f;
    if (j1 > 9) ej1 = 0.0f;
    j0 = max(j0, 0); j1 = min(j1, 9);

    #pragma unroll
    for (int l = 0; l < 3; l++) {
        const float* w1a = &W1s[l * 650 + j0 * 65];
        const float* w1b = &W1s[l * 650 + j1 * 65];
        const float* w2  = &W2s[l * 64];
        float acc = 0.0f;
        #pragma unroll 8
        for (int h = 0; h < 64; h++) {
            float z  = fmaf(ej0, w1a[h], ej1 * w1b[h]);
            float sl = __fdividef(z, 1.0f + __expf(-z));
            acc = fmaf(sl, w2[h], acc);
        }
        g_rad[l * EMAX + e] = acc * 0.125f;
    }
}

__global__ void scan_kernel(int n)
{
    __shared__ int warpsums[32];
    __shared__ int s_carry;
    int tid = threadIdx.x, lane = tid & 31, wid = tid >> 5;
    if (tid == 0) { s_carry = 0; g_off[0] = 0; }
    __syncthreads();
    for (int base = 0; base < n; base += 1024) {
        int i = base + tid;
        int v = (i < n) ? g_deg[i] : 0;
        int sc = v;
        #pragma unroll
        for (int o = 1; o < 32; o <<= 1) {
            int t = __shfl_up_sync(0xffffffffu, sc, o);
            if (lane >= o) sc += t;
        }
        if (lane == 31) warpsums[wid] = sc;
        __syncthreads();
        if (wid == 0) {
            int w = warpsums[lane];
            int ws = w;
            #pragma unroll
            for (int o = 1; o < 32; o <<= 1) {
                int t = __shfl_up_sync(0xffffffffu, ws, o);
                if (lane >= o) ws += t;
            }
            warpsums[lane] = ws - w;
        }
        __syncthreads();
        int incl = sc + warpsums[wid] + s_carry;
        if (i < n) { g_off[i + 1] = incl; g_cursor[i] = incl - v; }
        __syncthreads();
        if (tid == 1023) s_carry = incl;
        __syncthreads();
    }
}

__global__ void fill_kernel(const int* __restrict__ edst, int E)
{
    int e = blockIdx.x * blockDim.x + threadIdx.x;
    if (e >= E) return;
    float len = g_attr[e].w;
    if (len > 0.0f && len < 5.0f) {
        int p = atomicAdd(&g_cursor[edst[e]], 1);
        g_perm[p] = e;
    }
}

__global__ void sort_kernel(int N)
{
    int n = blockIdx.x * blockDim.x + threadIdx.x;
    if (n >= N) return;
    int s = g_off[n], t = g_off[n + 1];
    for (int i = s + 1; i < t; i++) {
        int key = g_perm[i];
        int j = i - 1;
        while (j >= s && g_perm[j] > key) { g_perm[j + 1] = g_perm[j]; j--; }
        g_perm[j + 1] = key;
    }
}

__global__ void embed_kernel(const float* __restrict__ x,
                             const float* __restrict__ We, int N)
{
    __shared__ float Ws[16 * 32];
    for (int i = threadIdx.x; i < 512; i += blockDim.x) Ws[i] = We[i];
    __syncthreads();
    int gid = blockIdx.x * blockDim.x + threadIdx.x;
    if (gid >= N * 32) return;
    int n = gid >> 5, k = gid & 31;
    const float* xr = x + n * 16;
    float acc = 0.0f;
    #pragma unroll
    for (int i = 0; i < 16; i++) acc = fmaf(__ldg(&xr[i]), Ws[i * 32 + k], acc);
    g_hA[gid] = acc;
}

__global__ __launch_bounds__(256) void layer_kernel(
    const float* __restrict__ h_in, float* __restrict__ h_out,
    const float* __restrict__ Wtp_l,
    const float* __restrict__ rad_l,
    const int*   __restrict__ esrc, int N)
{
    __shared__ float Wsh[4096];
    for (int i = threadIdx.x; i < 4096; i += blockDim.x) Wsh[i] = Wtp_l[i];
    __syncthreads();
    int lane = threadIdx.x & 31;
    int wpb = blockDim.x >> 5;
    int w0 = blockIdx.x * wpb + (threadIdx.x >> 5);
    int stride = gridDim.x * wpb;
    for (int n = w0; n < N; n += stride) {
        float s0 = 0.f, s1 = 0.f, s2 = 0.f, s3 = 0.f;
        int e0 = g_off[n], e1 = g_off[n + 1];
        for (int e = e0; e < e1; e++) {
            int eid = __ldg(&g_perm[e]);
            int src = __ldg(&esrc[eid]);
            float hs = __ldg(&h_in[src * 32 + lane]);
            float4 at = g_attr[eid];
            float r = __ldg(&rad_l[eid]);
            s0 = fmaf(r,        hs, s0);
            s1 = fmaf(r * at.x, hs, s1);
            s2 = fmaf(r * at.y, hs, s2);
            s3 = fmaf(r * at.z, hs, s3);
        }
        float ang = 0.0f;
        #pragma unroll
        for (int i = 0; i < 32; i++) {
            float v0 = __shfl_sync(0xffffffffu, s0, i);
            float v1 = __shfl_sync(0xffffffffu, s1, i);
            float v2 = __shfl_sync(0xffffffffu, s2, i);
            float v3 = __shfl_sync(0xffffffffu, s3, i);
            const float* w = &Wsh[i * 128];
            ang = fmaf(v0, w[lane],      ang);
            ang = fmaf(v1, w[32 + lane], ang);
            ang = fmaf(v2, w[64 + lane], ang);
            ang = fmaf(v3, w[96 + lane], ang);
        }
        h_out[n * 32 + lane] = h_in[n * 32 + lane] + COMB_NORM * ang;
    }
}

__global__ void pool_kernel(const float* __restrict__ h,
                            const float* __restrict__ ori,
                            const float* __restrict__ Wdec,
                            const int*   __restrict__ batch,
                            float* __restrict__ out, int N)
{
    int g = blockIdx.x;
    __shared__ int s_range[2];
    __shared__ float s_part[8][32];
    int tid = threadIdx.x, lane = tid & 31, wid = tid >> 5;
    if (tid < 2) {
        int key = g + tid;
        int lo = 0, hi = N;
        while (lo < hi) { int m = (lo + hi) >> 1; if (batch[m] < key) lo = m + 1; else hi = m; }
        s_range[tid] = lo;
    }
    __syncthreads();
    int st = s_range[0], en = s_range[1];
    float sum = 0.0f;
    for (int n = st + wid; n < en; n += 8) sum += __ldg(&h[n * 32 + lane]);
    s_part[wid][lane] = sum;
    __syncthreads();
    if (wid == 0) {
        float tot = 0.0f;
        #pragma unroll
        for (int w = 0; w < 8; w++) tot += s_part[w][lane];
        int cnt = en - st;
        float gk = tot / fmaxf((float)cnt, 1.0f);
        float c0 = gk * Wdec[lane * 4 + 0];
        float c1 = gk * Wdec[lane * 4 + 1];
        float c2 = gk * Wdec[lane * 4 + 2];
        float c3 = gk * Wdec[lane * 4 + 3];
        #pragma unroll
        for (int o = 16; o > 0; o >>= 1) {
            c0 += __shfl_xor_sync(0xffffffffu, c0, o);
            c1 += __shfl_xor_sync(0xffffffffu, c1, o);
            c2 += __shfl_xor_sync(0xffffffffu, c2, o);
            c3 += __shfl_xor_sync(0xffffffffu, c3, o);
        }
        if (lane == 0) {
            float th = ori[g * 2], ph = ori[g * 2 + 1];
            float sth = sinf(th), cth = cosf(th), sph = sinf(ph), cph = cosf(ph);
            float qx = sth * cph, qy = sth * sph, qz = cth;
            out[g] = c0 + SQRT3F * (c1 * qy + c2 * qz + c3 * qx);
        }
    }
}

extern "C" void kernel_launch(void* const* d_in, const int* in_sizes, int n_in,
                              void* d_out, int out_size)
{
    const float* pos     = (const float*)d_in[0];
    const float* x       = (const float*)d_in[1];
    const float* ori     = (const float*)d_in[2];
    const float* W_embed = (const float*)d_in[3];
    const float* W_tp    = (const float*)d_in[4];
    const float* W_fc1   = (const float*)d_in[5];
    const float* W_fc2   = (const float*)d_in[6];
    const float* W_dec   = (const float*)d_in[7];
    const int*   esrc    = (const int*)d_in[8];
    const int*   edst    = (const int*)d_in[9];
    const int*   batch   = (const int*)d_in[10];
    int N = in_sizes[10];
    int E = in_sizes[8];
    int G = in_sizes[2] / 2;
    float* out = (float*)d_out;

    void *degp, *hA, *hB, *radp;
    cudaGetSymbolAddress(&degp, g_deg);
    cudaGetSymbolAddress(&hA, g_hA);
    cudaGetSymbolAddress(&hB, g_hB);
    cudaGetSymbolAddress(&radp, g_rad);
    const float* rad = (const float*)radp;

    cudaMemsetAsync(degp, 0, (size_t)N * sizeof(int));
    pre_kernel<<<(E + 255) / 256, 256>>>(pos, esrc, edst, W_fc1, W_fc2, E);
    scan_kernel<<<1, 1024>>>(N);
    fill_kernel<<<(E + 255) / 256, 256>>>(edst, E);
    sort_kernel<<<(N + 255) / 256, 256>>>(N);
    embed_kernel<<<(N * 32 + 255) / 256, 256>>>(x, W_embed, N);

    layer_kernel<<<1184, 256>>>((const float*)hA, (float*)hB, W_tp + 0 * 4096, rad + 0 * EMAX, esrc, N);
    layer_kernel<<<1184, 256>>>((const float*)hB, (float*)hA, W_tp + 1 * 4096, rad + 1 * EMAX, esrc, N);
    layer_kernel<<<1184, 256>>>((const float*)hA, (float*)hB, W_tp + 2 * 4096, rad + 2 * EMAX, esrc, N);

    pool_kernel<<<G, 256>>>((const float*)hB, ori, W_dec, batch, out, N);
}

// round 3
// speedup vs baseline: 1.1457x; 1.1457x over previous
#include <cuda_runtime.h>
#include <math.h>

#define DD 32
#define NMAX 100000
#define EMAX 800000
#define TBINS 4096

// ---------------- static scratch ----------------
__device__ float  g_hA[NMAX * DD];
__device__ float  g_hB[NMAX * DD];
__device__ float4 g_attr[EMAX];          // (s3*vy/L, s3*vz/L, s3*vx/L, len)
__device__ float  g_tab[3 * (TBINS + 1)];// rad_l(len) lookup tables
__device__ int    g_deg[NMAX];
__device__ int    g_off[NMAX + 1];
__device__ int    g_cursor[NMAX];
__device__ int    g_perm[EMAX];
__device__ int    g_srcp[EMAX];          // src per packed (CSR-ordered) edge
__device__ float4 g_wpack[3 * EMAX];     // premultiplied rad*(1,ax,ay,az)

#define SQRT3F 1.7320508075688772f
#define SMOOTH_CF 8.4335730691f           // 1.14136 * e^2
#define COMB_NORM 0.022821773229382f      // tp_norm * agg_norm = 1/sqrt(128*15)
#define TAB_SCALE 819.2f                  // TBINS / 5

// ------------- radial MLP lookup-table builder (exact MLP, per length bin) --
__global__ void table_kernel(const float* __restrict__ W1,   // [3,10,64]
                             const float* __restrict__ W2)   // [3,64]
{
    int idx = blockIdx.x * blockDim.x + threadIdx.x;
    if (idx >= 3 * (TBINS + 1)) return;
    int l = idx / (TBINS + 1);
    int b = idx % (TBINS + 1);
    float len = (float)b * (5.0f / TBINS);

    float t  = len * 2.2f;               // len/step, step = 5/11
    int   j1 = (int)t;
    float d0 = t - (float)j1;
    float d1 = d0 - 1.0f;
    float ej0 = SMOOTH_CF * __expf(-(__fdividef(1.f, 1.f + d0) + __fdividef(1.f, 1.f - d0)));
    float ej1 = SMOOTH_CF * __expf(-(__fdividef(1.f, 1.f + d1) + __fdividef(1.f, 1.f - d1)));
    int j0 = j1 - 1;
    if (j0 < 0) ej0 = 0.0f;
    if (j0 > 9) ej0 = 0.0f;
    if (j1 > 9) ej1 = 0.0f;
    j0 = min(max(j0, 0), 9);
    j1 = min(max(j1, 0), 9);

    const float* w1a = W1 + l * 640 + j0 * 64;
    const float* w1b = W1 + l * 640 + j1 * 64;
    const float* w2  = W2 + l * 64;
    float acc = 0.0f;
    #pragma unroll 8
    for (int h = 0; h < 64; h++) {
        float z  = fmaf(ej0, w1a[h], ej1 * w1b[h]);
        float sl = __fdividef(z, 1.0f + __expf(-z));   // silu
        acc = fmaf(sl, w2[h], acc);
    }
    g_tab[idx] = acc * 0.125f;   // fc2_norm = 1/8
}

// ---------------- edge geometry + degree histogram -------------------------
__global__ void pre_kernel(const float* __restrict__ pos,
                           const int*   __restrict__ esrc,
                           const int*   __restrict__ edst,
                           int E)
{
    int e = blockIdx.x * blockDim.x + threadIdx.x;
    if (e >= E) return;
    int s = esrc[e], d = edst[e];
    float vx = pos[s * 3 + 0] - pos[d * 3 + 0];
    float vy = pos[s * 3 + 1] - pos[d * 3 + 1];
    float vz = pos[s * 3 + 2] - pos[d * 3 + 2];
    float len = sqrtf(vx * vx + vy * vy + vz * vz);
    float inv = __fdividef(SQRT3F, len + 1e-9f);
    g_attr[e] = make_float4(vy * inv, vz * inv, vx * inv, len);
    if (len > 0.0f && len < 5.0f)
        atomicAdd(&g_deg[d], 1);
}

// ---------------- single-block exclusive scan ------------------------------
__global__ void scan_kernel(int n)
{
    __shared__ int warpsums[32];
    __shared__ int s_carry;
    int tid = threadIdx.x, lane = tid & 31, wid = tid >> 5;
    if (tid == 0) { s_carry = 0; g_off[0] = 0; }
    __syncthreads();
    for (int base = 0; base < n; base += 1024) {
        int i = base + tid;
        int v = (i < n) ? g_deg[i] : 0;
        int sc = v;
        #pragma unroll
        for (int o = 1; o < 32; o <<= 1) {
            int t = __shfl_up_sync(0xffffffffu, sc, o);
            if (lane >= o) sc += t;
        }
        if (lane == 31) warpsums[wid] = sc;
        __syncthreads();
        if (wid == 0) {
            int w = warpsums[lane];
            int ws = w;
            #pragma unroll
            for (int o = 1; o < 32; o <<= 1) {
                int t = __shfl_up_sync(0xffffffffu, ws, o);
                if (lane >= o) ws += t;
            }
            warpsums[lane] = ws - w;
        }
        __syncthreads();
        int incl = sc + warpsums[wid] + s_carry;
        if (i < n) { g_off[i + 1] = incl; g_cursor[i] = incl - v; }
        __syncthreads();
        if (tid == 1023) s_carry = incl;
        __syncthreads();
    }
}

__global__ void fill_kernel(const int* __restrict__ edst, int E)
{
    int e = blockIdx.x * blockDim.x + threadIdx.x;
    if (e >= E) return;
    float len = g_attr[e].w;
    if (len > 0.0f && len < 5.0f) {
        int p = atomicAdd(&g_cursor[edst[e]], 1);
        g_perm[p] = e;
    }
}

__global__ void sort_kernel(int N)   // deterministic order within each node
{
    int n = blockIdx.x * blockDim.x + threadIdx.x;
    if (n >= N) return;
    int s = g_off[n], t = g_off[n + 1];
    for (int i = s + 1; i < t; i++) {
        int key = g_perm[i];
        int j = i - 1;
        while (j >= s && g_perm[j] > key) { g_perm[j + 1] = g_perm[j]; j--; }
        g_perm[j + 1] = key;
    }
}

// ---------------- pack CSR-ordered edge data (src + premultiplied weights) --
__global__ void pack_kernel(const int* __restrict__ esrc, int N, int E)
{
    int p = blockIdx.x * blockDim.x + threadIdx.x;
    if (p >= E) return;
    int tot = g_off[N];
    if (p >= tot) return;
    int eid = g_perm[p];
    float4 at = g_attr[eid];
    g_srcp[p] = esrc[eid];
    float u = at.w * TAB_SCALE;
    int b = (int)u;
    float fr = u - (float)b;
    #pragma unroll
    for (int l = 0; l < 3; l++) {
        float t0 = g_tab[l * (TBINS + 1) + b];
        float t1 = g_tab[l * (TBINS + 1) + b + 1];
        float r = fmaf(fr, t1 - t0, t0);
        g_wpack[l * EMAX + p] = make_float4(r, r * at.x, r * at.y, r * at.z);
    }
}

// ---------------- embedding ------------------------------------------------
__global__ void embed_kernel(const float* __restrict__ x,
                             const float* __restrict__ We, int N)
{
    __shared__ float Ws[16 * 32];
    for (int i = threadIdx.x; i < 512; i += blockDim.x) Ws[i] = We[i];
    __syncthreads();
    int gid = blockIdx.x * blockDim.x + threadIdx.x;
    if (gid >= N * 32) return;
    int n = gid >> 5, k = gid & 31;
    const float* xr = x + n * 16;
    float acc = 0.0f;
    #pragma unroll
    for (int i = 0; i < 16; i++) acc = fmaf(__ldg(&xr[i]), Ws[i * 32 + k], acc);
    g_hA[gid] = acc;
}

// ---------------- message-passing layer (warp per node) --------------------
__global__ __launch_bounds__(256) void layer_kernel(
    const float*  __restrict__ h_in, float* __restrict__ h_out,
    const float*  __restrict__ Wtp_l,   // [32,4,32]
    const float4* __restrict__ wpack_l, // [Eact]
    int N)
{
    __shared__ float Wsh[4096];
    for (int i = threadIdx.x; i < 4096; i += blockDim.x) Wsh[i] = Wtp_l[i];
    __syncthreads();
    int lane = threadIdx.x & 31;
    int wpb = blockDim.x >> 5;
    int w0 = blockIdx.x * wpb + (threadIdx.x >> 5);
    int stride = gridDim.x * wpb;
    for (int n = w0; n < N; n += stride) {
        float s0 = 0.f, s1 = 0.f, s2 = 0.f, s3 = 0.f;
        int e0 = g_off[n], e1 = g_off[n + 1];
        int p = e0;
        int src = 0; float4 w = make_float4(0, 0, 0, 0);
        if (p < e1) { src = __ldg(&g_srcp[p]); w = __ldg(&wpack_l[p]); }
        while (p < e1) {
            float hs = __ldg(&h_in[src * 32 + lane]);   // coalesced 128B gather
            int p2 = p + 1;
            int src2 = 0; float4 w2 = make_float4(0, 0, 0, 0);
            if (p2 < e1) { src2 = __ldg(&g_srcp[p2]); w2 = __ldg(&wpack_l[p2]); }
            s0 = fmaf(w.x, hs, s0);
            s1 = fmaf(w.y, hs, s1);
            s2 = fmaf(w.z, hs, s2);
            s3 = fmaf(w.w, hs, s3);
            src = src2; w = w2; p = p2;
        }
        // ang[lane] = sum_{i,a} s_a[i] * W[i,a,lane]
        float ang = 0.0f;
        #pragma unroll
        for (int i = 0; i < 32; i++) {
            float v0 = __shfl_sync(0xffffffffu, s0, i);
            float v1 = __shfl_sync(0xffffffffu, s1, i);
            float v2 = __shfl_sync(0xffffffffu, s2, i);
            float v3 = __shfl_sync(0xffffffffu, s3, i);
            const float* ww = &Wsh[i * 128];
            ang = fmaf(v0, ww[lane],      ang);
            ang = fmaf(v1, ww[32 + lane], ang);
            ang = fmaf(v2, ww[64 + lane], ang);
            ang = fmaf(v3, ww[96 + lane], ang);
        }
        h_out[n * 32 + lane] = h_in[n * 32 + lane] + COMB_NORM * ang;
    }
}

// ---------------- pooling + decoder ----------------------------------------
__global__ void pool_kernel(const float* __restrict__ h,
                            const float* __restrict__ ori,
                            const float* __restrict__ Wdec,
                            const int*   __restrict__ batch,
                            float* __restrict__ out, int N)
{
    int g = blockIdx.x;
    __shared__ int s_range[2];
    __shared__ float s_part[8][32];
    int tid = threadIdx.x, lane = tid & 31, wid = tid >> 5;
    if (tid < 2) {
        int key = g + tid;
        int lo = 0, hi = N;
        while (lo < hi) { int m = (lo + hi) >> 1; if (batch[m] < key) lo = m + 1; else hi = m; }
        s_range[tid] = lo;
    }
    __syncthreads();
    int st = s_range[0], en = s_range[1];
    float sum = 0.0f;
    for (int n = st + wid; n < en; n += 8) sum += __ldg(&h[n * 32 + lane]);
    s_part[wid][lane] = sum;
    __syncthreads();
    if (wid == 0) {
        float tot = 0.0f;
        #pragma unroll
        for (int w = 0; w < 8; w++) tot += s_part[w][lane];
        int cnt = en - st;
        float gk = tot / fmaxf((float)cnt, 1.0f);
        float c0 = gk * Wdec[lane * 4 + 0];
        float c1 = gk * Wdec[lane * 4 + 1];
        float c2 = gk * Wdec[lane * 4 + 2];
        float c3 = gk * Wdec[lane * 4 + 3];
        #pragma unroll
        for (int o = 16; o > 0; o >>= 1) {
            c0 += __shfl_xor_sync(0xffffffffu, c0, o);
            c1 += __shfl_xor_sync(0xffffffffu, c1, o);
            c2 += __shfl_xor_sync(0xffffffffu, c2, o);
            c3 += __shfl_xor_sync(0xffffffffu, c3, o);
        }
        if (lane == 0) {
            float th = ori[g * 2], ph = ori[g * 2 + 1];
            float sth = sinf(th), cth = cosf(th), sph = sinf(ph), cph = cosf(ph);
            float qx = sth * cph, qy = sth * sph, qz = cth;
            out[g] = c0 + SQRT3F * (c1 * qy + c2 * qz + c3 * qx);
        }
    }
}

// ---------------------------------------------------------------------------
extern "C" void kernel_launch(void* const* d_in, const int* in_sizes, int n_in,
                              void* d_out, int out_size)
{
    const float* pos     = (const float*)d_in[0];
    const float* x       = (const float*)d_in[1];
    const float* ori     = (const float*)d_in[2];
    const float* W_embed = (const float*)d_in[3];
    const float* W_tp    = (const float*)d_in[4];
    const float* W_fc1   = (const float*)d_in[5];
    const float* W_fc2   = (const float*)d_in[6];
    const float* W_dec   = (const float*)d_in[7];
    const int*   esrc    = (const int*)d_in[8];
    const int*   edst    = (const int*)d_in[9];
    const int*   batch   = (const int*)d_in[10];
    int N = in_sizes[10];
    int E = in_sizes[8];
    int G = in_sizes[2] / 2;
    float* out = (float*)d_out;

    void *degp, *hA, *hB, *wpk;
    cudaGetSymbolAddress(&degp, g_deg);
    cudaGetSymbolAddress(&hA, g_hA);
    cudaGetSymbolAddress(&hB, g_hB);
    cudaGetSymbolAddress(&wpk, g_wpack);
    const float4* wpack = (const float4*)wpk;

    cudaMemsetAsync(degp, 0, (size_t)N * sizeof(int));
    table_kernel<<<(3 * (TBINS + 1) + 255) / 256, 256>>>(W_fc1, W_fc2);
    pre_kernel<<<(E + 255) / 256, 256>>>(pos, esrc, edst, E);
    scan_kernel<<<1, 1024>>>(N);
    fill_kernel<<<(E + 255) / 256, 256>>>(edst, E);
    sort_kernel<<<(N + 255) / 256, 256>>>(N);
    pack_kernel<<<(E + 255) / 256, 256>>>(esrc, N, E);
    embed_kernel<<<(N * 32 + 255) / 256, 256>>>(x, W_embed, N);

    layer_kernel<<<1184, 256>>>((const float*)hA, (float*)hB, W_tp + 0 * 4096, wpack + 0 * EMAX, N);
    layer_kernel<<<1184, 256>>>((const float*)hB, (float*)hA, W_tp + 1 * 4096, wpack + 1 * EMAX, N);
    layer_kernel<<<1184, 256>>>((const float*)hA, (float*)hB, W_tp + 2 * 4096, wpack + 2 * EMAX, N);

    pool_kernel<<<G, 256>>>((const float*)hB, ori, W_dec, batch, out, N);
}

// round 4
// speedup vs baseline: 1.3475x; 1.1761x over previous
#include <cuda_runtime.h>
#include <math.h>

#define DD 32
#define NMAX 100000
#define EMAX 800000
#define TBINS 2048

// ---------------- static scratch ----------------
__device__ float  g_hA[NMAX * DD];
__device__ float  g_hB[NMAX * DD];
__device__ float4 g_attr[EMAX];          // (s3*vy/L, s3*vz/L, s3*vx/L, len)
__device__ float  g_len[EMAX];
__device__ float  g_tab[3 * (TBINS + 1)];// rad_l(len) lookup tables
__device__ int    g_deg[NMAX];
__device__ int    g_off[NMAX + 1];
__device__ int    g_cursor[NMAX];
__device__ int    g_perm[EMAX];
__device__ int    g_srcp[EMAX];          // src per packed (CSR-ordered) edge
__device__ float4 g_apack[EMAX];         // CSR-ordered (ax, ay, az, len)

#define SQRT3F 1.7320508075688772f
#define SMOOTH_CF 8.4335730691f           // 1.14136 * e^2
#define COMB_NORM 0.022821773229382f      // tp_norm * agg_norm = 1/sqrt(128*15)
#define TAB_SCALE 409.6f                  // TBINS / 5

// ------------- radial MLP lookup-table builder (exact MLP, per length bin) --
__global__ void table_kernel(const float* __restrict__ W1,   // [3,10,64]
                             const float* __restrict__ W2)   // [3,64]
{
    int idx = blockIdx.x * blockDim.x + threadIdx.x;
    if (idx >= 3 * (TBINS + 1)) return;
    int l = idx / (TBINS + 1);
    int b = idx % (TBINS + 1);
    float len = (float)b * (5.0f / TBINS);

    float t  = len * 2.2f;               // len/step, step = 5/11
    int   j1 = (int)t;
    float d0 = t - (float)j1;
    float d1 = d0 - 1.0f;
    float ej0 = SMOOTH_CF * __expf(-(__fdividef(1.f, 1.f + d0) + __fdividef(1.f, 1.f - d0)));
    float ej1 = SMOOTH_CF * __expf(-(__fdividef(1.f, 1.f + d1) + __fdividef(1.f, 1.f - d1)));
    int j0 = j1 - 1;
    if (j0 < 0) ej0 = 0.0f;
    if (j0 > 9) ej0 = 0.0f;
    if (j1 > 9) ej1 = 0.0f;
    j0 = min(max(j0, 0), 9);
    j1 = min(max(j1, 0), 9);

    const float* w1a = W1 + l * 640 + j0 * 64;
    const float* w1b = W1 + l * 640 + j1 * 64;
    const float* w2  = W2 + l * 64;
    float acc = 0.0f;
    #pragma unroll 8
    for (int h = 0; h < 64; h++) {
        float z  = fmaf(ej0, w1a[h], ej1 * w1b[h]);
        float sl = __fdividef(z, 1.0f + __expf(-z));   // silu
        acc = fmaf(sl, w2[h], acc);
    }
    g_tab[idx] = acc * 0.125f;   // fc2_norm = 1/8
}

// ---------------- edge geometry + degree histogram -------------------------
__global__ void pre_kernel(const float* __restrict__ pos,
                           const int*   __restrict__ esrc,
                           const int*   __restrict__ edst,
                           int E)
{
    int e = blockIdx.x * blockDim.x + threadIdx.x;
    if (e >= E) return;
    int s = esrc[e], d = edst[e];
    float vx = pos[s * 3 + 0] - pos[d * 3 + 0];
    float vy = pos[s * 3 + 1] - pos[d * 3 + 1];
    float vz = pos[s * 3 + 2] - pos[d * 3 + 2];
    float len = sqrtf(vx * vx + vy * vy + vz * vz);
    float inv = __fdividef(SQRT3F, len + 1e-9f);
    g_attr[e] = make_float4(vy * inv, vz * inv, vx * inv, len);
    g_len[e] = len;
    if (len > 0.0f && len < 5.0f)
        atomicAdd(&g_deg[d], 1);
}

// ---------------- single-block exclusive scan, 4 elems / thread ------------
__global__ void scan_kernel(int n)
{
    __shared__ int warpsums[32];
    __shared__ int s_carry;
    int tid = threadIdx.x, lane = tid & 31, wid = tid >> 5;
    if (tid == 0) { s_carry = 0; g_off[0] = 0; }
    __syncthreads();
    const int4* deg4 = (const int4*)g_deg;
    for (int base = 0; base < n; base += 4096) {
        int i0 = base + tid * 4;
        int4 v = make_int4(0, 0, 0, 0);
        if (i0 + 3 < n) v = deg4[i0 >> 2];
        else {
            if (i0 + 0 < n) v.x = g_deg[i0 + 0];
            if (i0 + 1 < n) v.y = g_deg[i0 + 1];
            if (i0 + 2 < n) v.z = g_deg[i0 + 2];
            if (i0 + 3 < n) v.w = g_deg[i0 + 3];
        }
        int tot = v.x + v.y + v.z + v.w;
        int sc = tot;
        #pragma unroll
        for (int o = 1; o < 32; o <<= 1) {
            int t = __shfl_up_sync(0xffffffffu, sc, o);
            if (lane >= o) sc += t;
        }
        if (lane == 31) warpsums[wid] = sc;
        __syncthreads();
        if (wid == 0) {
            int w = warpsums[lane];
            int ws = w;
            #pragma unroll
            for (int o = 1; o < 32; o <<= 1) {
                int t = __shfl_up_sync(0xffffffffu, ws, o);
                if (lane >= o) ws += t;
            }
            warpsums[lane] = ws - w;
        }
        __syncthreads();
        int excl = sc - tot + warpsums[wid] + s_carry;   // exclusive at i0
        int p0 = excl;
        int p1 = p0 + v.x;
        int p2 = p1 + v.y;
        int p3 = p2 + v.z;
        int p4 = p3 + v.w;
        if (i0 + 0 < n) { g_cursor[i0 + 0] = p0; g_off[i0 + 1] = p1; }
        if (i0 + 1 < n) { g_cursor[i0 + 1] = p1; g_off[i0 + 2] = p2; }
        if (i0 + 2 < n) { g_cursor[i0 + 2] = p2; g_off[i0 + 3] = p3; }
        if (i0 + 3 < n) { g_cursor[i0 + 3] = p3; g_off[i0 + 4] = p4; }
        __syncthreads();
        if (tid == 1023) s_carry = p4;
        __syncthreads();
    }
}

__global__ void fill_kernel(const int* __restrict__ edst, int E)
{
    int e = blockIdx.x * blockDim.x + threadIdx.x;
    if (e >= E) return;
    float len = g_len[e];
    if (len > 0.0f && len < 5.0f) {
        int p = atomicAdd(&g_cursor[edst[e]], 1);
        g_perm[p] = e;
    }
}

__global__ void sort_kernel(int N)   // deterministic order within each node
{
    int n = blockIdx.x * blockDim.x + threadIdx.x;
    if (n >= N) return;
    int s = g_off[n], t = g_off[n + 1];
    for (int i = s + 1; i < t; i++) {
        int key = g_perm[i];
        int j = i - 1;
        while (j >= s && g_perm[j] > key) { g_perm[j + 1] = g_perm[j]; j--; }
        g_perm[j + 1] = key;
    }
}

// ---------------- pack CSR-ordered edge data -------------------------------
__global__ void pack_kernel(const int* __restrict__ esrc, int N, int E)
{
    int p = blockIdx.x * blockDim.x + threadIdx.x;
    if (p >= E) return;
    int tot = g_off[N];
    if (p >= tot) return;
    int eid = g_perm[p];
    g_srcp[p] = esrc[eid];
    g_apack[p] = g_attr[eid];   // (ax, ay, az, len)
}

// ---------------- embedding ------------------------------------------------
__global__ void embed_kernel(const float* __restrict__ x,
                             const float* __restrict__ We, int N)
{
    __shared__ float Ws[16 * 32];
    for (int i = threadIdx.x; i < 512; i += blockDim.x) Ws[i] = We[i];
    __syncthreads();
    int gid = blockIdx.x * blockDim.x + threadIdx.x;
    if (gid >= N * 32) return;
    int n = gid >> 5, k = gid & 31;
    const float* xr = x + n * 16;
    float acc = 0.0f;
    #pragma unroll
    for (int i = 0; i < 16; i++) acc = fmaf(__ldg(&xr[i]), Ws[i * 32 + k], acc);
    g_hA[gid] = acc;
}

// ---------------- message-passing layer (warp per node) --------------------
__global__ __launch_bounds__(256) void layer_kernel(
    const float*  __restrict__ h_in, float* __restrict__ h_out,
    const float*  __restrict__ Wtp_l,   // [32,4,32]
    const float*  __restrict__ tab_l,   // [TBINS+1]
    int N)
{
    __shared__ float4 Wsh4[1024];            // [i][k] -> (W[i,0,k..3])
    __shared__ float  Tsh[TBINS + 1];
    __shared__ float4 s_sm[8 * 32];          // per-warp accumulator staging

    for (int t = threadIdx.x; t < 1024; t += blockDim.x) {
        int i = t >> 5, k = t & 31;
        const float* w = Wtp_l + i * 128;
        Wsh4[t] = make_float4(w[k], w[32 + k], w[64 + k], w[96 + k]);
    }
    for (int t = threadIdx.x; t < TBINS + 1; t += blockDim.x) Tsh[t] = tab_l[t];
    __syncthreads();

    int lane = threadIdx.x & 31;
    int wloc = threadIdx.x >> 5;
    int wpb = blockDim.x >> 5;
    int w0 = blockIdx.x * wpb + wloc;
    int stride = gridDim.x * wpb;
    float4* s_me = &s_sm[wloc * 32];

    for (int n = w0; n < N; n += stride) {
        float c0 = 0.f, c1 = 0.f, c2 = 0.f, c3 = 0.f;
        int e0 = g_off[n], e1 = g_off[n + 1];
        int p = e0;
        for (; p + 4 <= e1; p += 4) {
            int    sA = __ldg(&g_srcp[p]);
            int    sB = __ldg(&g_srcp[p + 1]);
            int    sC = __ldg(&g_srcp[p + 2]);
            int    sD = __ldg(&g_srcp[p + 3]);
            float4 aA = __ldg(&g_apack[p]);
            float4 aB = __ldg(&g_apack[p + 1]);
            float4 aC = __ldg(&g_apack[p + 2]);
            float4 aD = __ldg(&g_apack[p + 3]);
            float hA = __ldg(&h_in[sA * 32 + lane]);
            float hB = __ldg(&h_in[sB * 32 + lane]);
            float hC = __ldg(&h_in[sC * 32 + lane]);
            float hD = __ldg(&h_in[sD * 32 + lane]);
            float uA = aA.w * TAB_SCALE; int bA = (int)uA; float fA = uA - (float)bA;
            float uB = aB.w * TAB_SCALE; int bB = (int)uB; float fB = uB - (float)bB;
            float uC = aC.w * TAB_SCALE; int bC = (int)uC; float fC = uC - (float)bC;
            float uD = aD.w * TAB_SCALE; int bD = (int)uD; float fD = uD - (float)bD;
            float rA = fmaf(fA, Tsh[bA + 1] - Tsh[bA], Tsh[bA]);
            float rB = fmaf(fB, Tsh[bB + 1] - Tsh[bB], Tsh[bB]);
            float rC = fmaf(fC, Tsh[bC + 1] - Tsh[bC], Tsh[bC]);
            float rD = fmaf(fD, Tsh[bD + 1] - Tsh[bD], Tsh[bD]);
            c0 = fmaf(rA, hA, c0); c1 = fmaf(rA * aA.x, hA, c1);
            c2 = fmaf(rA * aA.y, hA, c2); c3 = fmaf(rA * aA.z, hA, c3);
            c0 = fmaf(rB, hB, c0); c1 = fmaf(rB * aB.x, hB, c1);
            c2 = fmaf(rB * aB.y, hB, c2); c3 = fmaf(rB * aB.z, hB, c3);
            c0 = fmaf(rC, hC, c0); c1 = fmaf(rC * aC.x, hC, c1);
            c2 = fmaf(rC * aC.y, hC, c2); c3 = fmaf(rC * aC.z, hC, c3);
            c0 = fmaf(rD, hD, c0); c1 = fmaf(rD * aD.x, hD, c1);
            c2 = fmaf(rD * aD.y, hD, c2); c3 = fmaf(rD * aD.z, hD, c3);
        }
        for (; p < e1; p++) {
            int    s = __ldg(&g_srcp[p]);
            float4 a = __ldg(&g_apack[p]);
            float  h = __ldg(&h_in[s * 32 + lane]);
            float u = a.w * TAB_SCALE; int b = (int)u; float f = u - (float)b;
            float r = fmaf(f, Tsh[b + 1] - Tsh[b], Tsh[b]);
            c0 = fmaf(r, h, c0); c1 = fmaf(r * a.x, h, c1);
            c2 = fmaf(r * a.y, h, c2); c3 = fmaf(r * a.z, h, c3);
        }
        // stage accumulators: s_me[i] = (c0,c1,c2,c3) of lane i
        s_me[lane] = make_float4(c0, c1, c2, c3);
        __syncwarp();
        // ang[lane] = sum_i dot(s_me[i], Wsh4[i*32+lane])
        float ang = 0.0f;
        #pragma unroll
        for (int i = 0; i < 32; i++) {
            float4 sv = s_me[i];                 // broadcast LDS.128
            float4 wv = Wsh4[i * 32 + lane];     // conflict-free LDS.128
            ang = fmaf(sv.x, wv.x, ang);
            ang = fmaf(sv.y, wv.y, ang);
            ang = fmaf(sv.z, wv.z, ang);
            ang = fmaf(sv.w, wv.w, ang);
        }
        __syncwarp();
        h_out[n * 32 + lane] = h_in[n * 32 + lane] + COMB_NORM * ang;
    }
}

// ---------------- pooling + decoder ----------------------------------------
__global__ void pool_kernel(const float* __restrict__ h,
                            const float* __restrict__ ori,
                            const float* __restrict__ Wdec,
                            const int*   __restrict__ batch,
                            float* __restrict__ out, int N)
{
    int g = blockIdx.x;
    __shared__ int s_range[2];
    __shared__ float s_part[8][32];
    int tid = threadIdx.x, lane = tid & 31, wid = tid >> 5;
    if (tid < 2) {
        int key = g + tid;
        int lo = 0, hi = N;
        while (lo < hi) { int m = (lo + hi) >> 1; if (batch[m] < key) lo = m + 1; else hi = m; }
        s_range[tid] = lo;
    }
    __syncthreads();
    int st = s_range[0], en = s_range[1];
    float sum = 0.0f;
    for (int n = st + wid; n < en; n += 8) sum += __ldg(&h[n * 32 + lane]);
    s_part[wid][lane] = sum;
    __syncthreads();
    if (wid == 0) {
        float tot = 0.0f;
        #pragma unroll
        for (int w = 0; w < 8; w++) tot += s_part[w][lane];
        int cnt = en - st;
        float gk = tot / fmaxf((float)cnt, 1.0f);
        float c0 = gk * Wdec[lane * 4 + 0];
        float c1 = gk * Wdec[lane * 4 + 1];
        float c2 = gk * Wdec[lane * 4 + 2];
        float c3 = gk * Wdec[lane * 4 + 3];
        #pragma unroll
        for (int o = 16; o > 0; o >>= 1) {
            c0 += __shfl_xor_sync(0xffffffffu, c0, o);
            c1 += __shfl_xor_sync(0xffffffffu, c1, o);
            c2 += __shfl_xor_sync(0xffffffffu, c2, o);
            c3 += __shfl_xor_sync(0xffffffffu, c3, o);
        }
        if (lane == 0) {
            float th = ori[g * 2], ph = ori[g * 2 + 1];
            float sth = sinf(th), cth = cosf(th), sph = sinf(ph), cph = cosf(ph);
            float qx = sth * cph, qy = sth * sph, qz = cth;
            out[g] = c0 + SQRT3F * (c1 * qy + c2 * qz + c3 * qx);
        }
    }
}

// ---------------------------------------------------------------------------
extern "C" void kernel_launch(void* const* d_in, const int* in_sizes, int n_in,
                              void* d_out, int out_size)
{
    const float* pos     = (const float*)d_in[0];
    const float* x       = (const float*)d_in[1];
    const float* ori     = (const float*)d_in[2];
    const float* W_embed = (const float*)d_in[3];
    const float* W_tp    = (const float*)d_in[4];
    const float* W_fc1   = (const float*)d_in[5];
    const float* W_fc2   = (const float*)d_in[6];
    const float* W_dec   = (const float*)d_in[7];
    const int*   esrc    = (const int*)d_in[8];
    const int*   edst    = (const int*)d_in[9];
    const int*   batch   = (const int*)d_in[10];
    int N = in_sizes[10];
    int E = in_sizes[8];
    int G = in_sizes[2] / 2;
    float* out = (float*)d_out;

    void *degp, *hA, *hB, *tabp;
    cudaGetSymbolAddress(&degp, g_deg);
    cudaGetSymbolAddress(&hA, g_hA);
    cudaGetSymbolAddress(&hB, g_hB);
    cudaGetSymbolAddress(&tabp, g_tab);
    const float* tab = (const float*)tabp;

    cudaMemsetAsync(degp, 0, (size_t)N * sizeof(int));
    table_kernel<<<(3 * (TBINS + 1) + 255) / 256, 256>>>(W_fc1, W_fc2);
    pre_kernel<<<(E + 255) / 256, 256>>>(pos, esrc, edst, E);
    scan_kernel<<<1, 1024>>>(N);
    fill_kernel<<<(E + 255) / 256, 256>>>(edst, E);
    sort_kernel<<<(N + 255) / 256, 256>>>(N);
    pack_kernel<<<(E + 255) / 256, 256>>>(esrc, N, E);
    embed_kernel<<<(N * 32 + 255) / 256, 256>>>(x, W_embed, N);

    layer_kernel<<<1184, 256>>>((const float*)hA, (float*)hB, W_tp + 0 * 4096, tab + 0 * (TBINS + 1), N);
    layer_kernel<<<1184, 256>>>((const float*)hB, (float*)hA, W_tp + 1 * 4096, tab + 1 * (TBINS + 1), N);
    layer_kernel<<<1184, 256>>>((const float*)hA, (float*)hB, W_tp + 2 * 4096, tab + 2 * (TBINS + 1), N);

    pool_kernel<<<G, 256>>>((const float*)hB, ori, W_dec, batch, out, N);
}

// round 5
// speedup vs baseline: 1.5779x; 1.1710x over previous
#include <cuda_runtime.h>
#include <math.h>

#define DD 32
#define NMAX 100000
#define EMAX 800000
#define TBINS 2048
#define NB 8          // nodes per warp batch in layer kernel

// ---------------- static scratch ----------------
__device__ float  g_hA[NMAX * DD];
__device__ float  g_hB[NMAX * DD];
__device__ float4 g_attr[EMAX];          // (s3*vy/L, s3*vz/L, s3*vx/L, len)
__device__ float  g_len[EMAX];
__device__ float  g_tab[3 * (TBINS + 1)];
__device__ int    g_deg[NMAX];
__device__ int    g_off[NMAX + 1];
__device__ int    g_cursor[NMAX];
__device__ int    g_perm[EMAX];
__device__ int    g_srcp[EMAX];
__device__ float4 g_apack[EMAX];         // CSR-ordered (ax, ay, az, len)

#define SQRT3F 1.7320508075688772f
#define SMOOTH_CF 8.4335730691f
#define COMB_NORM 0.022821773229382f      // 1/sqrt(128*15)
#define TAB_SCALE 409.6f                  // TBINS / 5

// ------------- radial MLP lookup-table builder ----------------------------
__global__ void table_kernel(const float* __restrict__ W1,
                             const float* __restrict__ W2)
{
    int idx = blockIdx.x * blockDim.x + threadIdx.x;
    if (idx >= 3 * (TBINS + 1)) return;
    int l = idx / (TBINS + 1);
    int b = idx % (TBINS + 1);
    float len = (float)b * (5.0f / TBINS);

    float t  = len * 2.2f;
    int   j1 = (int)t;
    float d0 = t - (float)j1;
    float d1 = d0 - 1.0f;
    float ej0 = SMOOTH_CF * __expf(-(__fdividef(1.f, 1.f + d0) + __fdividef(1.f, 1.f - d0)));
    float ej1 = SMOOTH_CF * __expf(-(__fdividef(1.f, 1.f + d1) + __fdividef(1.f, 1.f - d1)));
    int j0 = j1 - 1;
    if (j0 < 0) ej0 = 0.0f;
    if (j0 > 9) ej0 = 0.0f;
    if (j1 > 9) ej1 = 0.0f;
    j0 = min(max(j0, 0), 9);
    j1 = min(max(j1, 0), 9);

    const float* w1a = W1 + l * 640 + j0 * 64;
    const float* w1b = W1 + l * 640 + j1 * 64;
    const float* w2  = W2 + l * 64;
    float acc = 0.0f;
    #pragma unroll 8
    for (int h = 0; h < 64; h++) {
        float z  = fmaf(ej0, w1a[h], ej1 * w1b[h]);
        float sl = __fdividef(z, 1.0f + __expf(-z));
        acc = fmaf(sl, w2[h], acc);
    }
    g_tab[idx] = acc * 0.125f;
}

// ---------------- edge geometry + degree histogram -------------------------
__global__ void pre_kernel(const float* __restrict__ pos,
                           const int*   __restrict__ esrc,
                           const int*   __restrict__ edst,
                           int E)
{
    int e = blockIdx.x * blockDim.x + threadIdx.x;
    if (e >= E) return;
    int s = esrc[e], d = edst[e];
    float vx = pos[s * 3 + 0] - pos[d * 3 + 0];
    float vy = pos[s * 3 + 1] - pos[d * 3 + 1];
    float vz = pos[s * 3 + 2] - pos[d * 3 + 2];
    float len = sqrtf(vx * vx + vy * vy + vz * vz);
    float inv = __fdividef(SQRT3F, len + 1e-9f);
    g_attr[e] = make_float4(vy * inv, vz * inv, vx * inv, len);
    g_len[e] = len;
    if (len > 0.0f && len < 5.0f)
        atomicAdd(&g_deg[d], 1);
}

// ---------------- single-block exclusive scan, 4 elems / thread ------------
__global__ void scan_kernel(int n)
{
    __shared__ int warpsums[32];
    __shared__ int s_carry;
    int tid = threadIdx.x, lane = tid & 31, wid = tid >> 5;
    if (tid == 0) { s_carry = 0; g_off[0] = 0; }
    __syncthreads();
    const int4* deg4 = (const int4*)g_deg;
    for (int base = 0; base < n; base += 4096) {
        int i0 = base + tid * 4;
        int4 v = make_int4(0, 0, 0, 0);
        if (i0 + 3 < n) v = deg4[i0 >> 2];
        else {
            if (i0 + 0 < n) v.x = g_deg[i0 + 0];
            if (i0 + 1 < n) v.y = g_deg[i0 + 1];
            if (i0 + 2 < n) v.z = g_deg[i0 + 2];
            if (i0 + 3 < n) v.w = g_deg[i0 + 3];
        }
        int tot = v.x + v.y + v.z + v.w;
        int sc = tot;
        #pragma unroll
        for (int o = 1; o < 32; o <<= 1) {
            int t = __shfl_up_sync(0xffffffffu, sc, o);
            if (lane >= o) sc += t;
        }
        if (lane == 31) warpsums[wid] = sc;
        __syncthreads();
        if (wid == 0) {
            int w = warpsums[lane];
            int ws = w;
            #pragma unroll
            for (int o = 1; o < 32; o <<= 1) {
                int t = __shfl_up_sync(0xffffffffu, ws, o);
                if (lane >= o) ws += t;
            }
            warpsums[lane] = ws - w;
        }
        __syncthreads();
        int excl = sc - tot + warpsums[wid] + s_carry;
        int p0 = excl;
        int p1 = p0 + v.x;
        int p2 = p1 + v.y;
        int p3 = p2 + v.z;
        int p4 = p3 + v.w;
        if (i0 + 0 < n) { g_cursor[i0 + 0] = p0; g_off[i0 + 1] = p1; }
        if (i0 + 1 < n) { g_cursor[i0 + 1] = p1; g_off[i0 + 2] = p2; }
        if (i0 + 2 < n) { g_cursor[i0 + 2] = p2; g_off[i0 + 3] = p3; }
        if (i0 + 3 < n) { g_cursor[i0 + 3] = p3; g_off[i0 + 4] = p4; }
        __syncthreads();
        if (tid == 1023) s_carry = p4;
        __syncthreads();
    }
}

__global__ void fill_kernel(const int* __restrict__ edst, int E)
{
    int e = blockIdx.x * blockDim.x + threadIdx.x;
    if (e >= E) return;
    float len = g_len[e];
    if (len > 0.0f && len < 5.0f) {
        int p = atomicAdd(&g_cursor[edst[e]], 1);
        g_perm[p] = e;
    }
}

__global__ void sort_kernel(int N)
{
    int n = blockIdx.x * blockDim.x + threadIdx.x;
    if (n >= N) return;
    int s = g_off[n], t = g_off[n + 1];
    for (int i = s + 1; i < t; i++) {
        int key = g_perm[i];
        int j = i - 1;
        while (j >= s && g_perm[j] > key) { g_perm[j + 1] = g_perm[j]; j--; }
        g_perm[j + 1] = key;
    }
}

// ---------------- pack CSR-ordered edge data -------------------------------
__global__ void pack_kernel(const int* __restrict__ esrc, int N, int E)
{
    int p = blockIdx.x * blockDim.x + threadIdx.x;
    if (p >= E) return;
    int tot = g_off[N];
    if (p >= tot) return;
    int eid = g_perm[p];
    g_srcp[p] = esrc[eid];
    g_apack[p] = g_attr[eid];
}

// ---------------- embedding ------------------------------------------------
__global__ void embed_kernel(const float* __restrict__ x,
                             const float* __restrict__ We, int N)
{
    __shared__ float Ws[16 * 32];
    for (int i = threadIdx.x; i < 512; i += blockDim.x) Ws[i] = We[i];
    __syncthreads();
    int gid = blockIdx.x * blockDim.x + threadIdx.x;
    if (gid >= N * 32) return;
    int n = gid >> 5, k = gid & 31;
    const float* xr = x + n * 16;
    float acc = 0.0f;
    #pragma unroll
    for (int i = 0; i < 16; i++) acc = fmaf(__ldg(&xr[i]), Ws[i * 32 + k], acc);
    g_hA[gid] = acc;
}

// ---------------- message-passing layer (warp per 8-node batch) ------------
__global__ __launch_bounds__(256) void layer_kernel(
    const float*  __restrict__ h_in, float* __restrict__ h_out,
    const float*  __restrict__ Wtp_l,   // [32,4,32]
    const float*  __restrict__ tab_l,   // [TBINS+1]
    int N)
{
    __shared__ float4 Wsh4[1024];              // Wsh4[i*32+k] = W[i, 0..3, k]
    __shared__ float  Tsh[TBINS + 1];
    __shared__ float4 s_sm[8 * NB * 32];       // 8 warps x NB nodes x 32 ch

    // coalesced linear stage of W into (reused) s_sm, then transpose in smem
    {
        float* stage = (float*)s_sm;           // 16KB of the 32KB region
        for (int t = threadIdx.x; t < 4096; t += blockDim.x) stage[t] = Wtp_l[t];
        __syncthreads();
        for (int t = threadIdx.x; t < 1024; t += blockDim.x) {
            int i = t >> 5, k = t & 31;
            const float* w = stage + i * 128;
            Wsh4[t] = make_float4(w[k], w[32 + k], w[64 + k], w[96 + k]);
        }
    }
    for (int t = threadIdx.x; t < TBINS + 1; t += blockDim.x) Tsh[t] = tab_l[t];
    __syncthreads();

    int lane = threadIdx.x & 31;
    int wloc = threadIdx.x >> 5;
    int wpb = blockDim.x >> 5;
    int w0 = blockIdx.x * wpb + wloc;
    int stride = gridDim.x * wpb;
    float4* s_b = &s_sm[wloc * NB * 32];

    int nBatches = (N + NB - 1) / NB;
    for (int b = w0; b < nBatches; b += stride) {
        int n0 = b * NB;
        // --- aggregate edges for each node in the batch ---
        #pragma unroll 1
        for (int nd = 0; nd < NB; nd++) {
            int n = n0 + nd;
            float c0 = 0.f, c1 = 0.f, c2 = 0.f, c3 = 0.f;
            if (n < N) {
                int e0 = g_off[n], e1 = g_off[n + 1];
                int p = e0;
                for (; p + 4 <= e1; p += 4) {
                    int    sA = __ldg(&g_srcp[p]);
                    int    sB = __ldg(&g_srcp[p + 1]);
                    int    sC = __ldg(&g_srcp[p + 2]);
                    int    sD = __ldg(&g_srcp[p + 3]);
                    float4 aA = __ldg(&g_apack[p]);
                    float4 aB = __ldg(&g_apack[p + 1]);
                    float4 aC = __ldg(&g_apack[p + 2]);
                    float4 aD = __ldg(&g_apack[p + 3]);
                    float hA = __ldg(&h_in[sA * 32 + lane]);
                    float hB = __ldg(&h_in[sB * 32 + lane]);
                    float hC = __ldg(&h_in[sC * 32 + lane]);
                    float hD = __ldg(&h_in[sD * 32 + lane]);
                    float uA = aA.w * TAB_SCALE; int bA = (int)uA; float fA = uA - (float)bA;
                    float uB = aB.w * TAB_SCALE; int bB = (int)uB; float fB = uB - (float)bB;
                    float uC = aC.w * TAB_SCALE; int bC = (int)uC; float fC = uC - (float)bC;
                    float uD = aD.w * TAB_SCALE; int bD = (int)uD; float fD = uD - (float)bD;
                    float rA = fmaf(fA, Tsh[bA + 1] - Tsh[bA], Tsh[bA]);
                    float rB = fmaf(fB, Tsh[bB + 1] - Tsh[bB], Tsh[bB]);
                    float rC = fmaf(fC, Tsh[bC + 1] - Tsh[bC], Tsh[bC]);
                    float rD = fmaf(fD, Tsh[bD + 1] - Tsh[bD], Tsh[bD]);
                    c0 = fmaf(rA, hA, c0); c1 = fmaf(rA * aA.x, hA, c1);
                    c2 = fmaf(rA * aA.y, hA, c2); c3 = fmaf(rA * aA.z, hA, c3);
                    c0 = fmaf(rB, hB, c0); c1 = fmaf(rB * aB.x, hB, c1);
                    c2 = fmaf(rB * aB.y, hB, c2); c3 = fmaf(rB * aB.z, hB, c3);
                    c0 = fmaf(rC, hC, c0); c1 = fmaf(rC * aC.x, hC, c1);
                    c2 = fmaf(rC * aC.y, hC, c2); c3 = fmaf(rC * aC.z, hC, c3);
                    c0 = fmaf(rD, hD, c0); c1 = fmaf(rD * aD.x, hD, c1);
                    c2 = fmaf(rD * aD.y, hD, c2); c3 = fmaf(rD * aD.z, hD, c3);
                }
                for (; p < e1; p++) {
                    int    s = __ldg(&g_srcp[p]);
                    float4 a = __ldg(&g_apack[p]);
                    float  h = __ldg(&h_in[s * 32 + lane]);
                    float u = a.w * TAB_SCALE; int bb = (int)u; float f = u - (float)bb;
                    float r = fmaf(f, Tsh[bb + 1] - Tsh[bb], Tsh[bb]);
                    c0 = fmaf(r, h, c0); c1 = fmaf(r * a.x, h, c1);
                    c2 = fmaf(r * a.y, h, c2); c3 = fmaf(r * a.z, h, c3);
                }
            }
            s_b[nd * 32 + lane] = make_float4(c0, c1, c2, c3);
        }
        __syncwarp();
        // --- transform: ang[nd][lane] = sum_i dot(s_b[nd][i], Wsh4[i][lane]) ---
        float ang[NB];
        #pragma unroll
        for (int nd = 0; nd < NB; nd++) ang[nd] = 0.0f;
        #pragma unroll 8
        for (int i = 0; i < 32; i++) {
            float4 wv = Wsh4[i * 32 + lane];    // 1 LDS.128 amortized over NB
            #pragma unroll
            for (int nd = 0; nd < NB; nd++) {
                float4 sv = s_b[nd * 32 + i];   // broadcast LDS.128
                ang[nd] = fmaf(sv.x, wv.x, ang[nd]);
                ang[nd] = fmaf(sv.y, wv.y, ang[nd]);
                ang[nd] = fmaf(sv.z, wv.z, ang[nd]);
                ang[nd] = fmaf(sv.w, wv.w, ang[nd]);
            }
        }
        __syncwarp();
        #pragma unroll
        for (int nd = 0; nd < NB; nd++) {
            int n = n0 + nd;
            if (n < N)
                h_out[n * 32 + lane] = h_in[n * 32 + lane] + COMB_NORM * ang[nd];
        }
    }
}

// ---------------- pooling + decoder ----------------------------------------
__global__ void pool_kernel(const float* __restrict__ h,
                            const float* __restrict__ ori,
                            const float* __restrict__ Wdec,
                            const int*   __restrict__ batch,
                            float* __restrict__ out, int N)
{
    int g = blockIdx.x;
    __shared__ int s_range[2];
    __shared__ float s_part[8][32];
    int tid = threadIdx.x, lane = tid & 31, wid = tid >> 5;
    if (tid < 2) {
        int key = g + tid;
        int lo = 0, hi = N;
        while (lo < hi) { int m = (lo + hi) >> 1; if (batch[m] < key) lo = m + 1; else hi = m; }
        s_range[tid] = lo;
    }
    __syncthreads();
    int st = s_range[0], en = s_range[1];
    float sum = 0.0f;
    for (int n = st + wid; n < en; n += 8) sum += __ldg(&h[n * 32 + lane]);
    s_part[wid][lane] = sum;
    __syncthreads();
    if (wid == 0) {
        float tot = 0.0f;
        #pragma unroll
        for (int w = 0; w < 8; w++) tot += s_part[w][lane];
        int cnt = en - st;
        float gk = tot / fmaxf((float)cnt, 1.0f);
        float c0 = gk * Wdec[lane * 4 + 0];
        float c1 = gk * Wdec[lane * 4 + 1];
        float c2 = gk * Wdec[lane * 4 + 2];
        float c3 = gk * Wdec[lane * 4 + 3];
        #pragma unroll
        for (int o = 16; o > 0; o >>= 1) {
            c0 += __shfl_xor_sync(0xffffffffu, c0, o);
            c1 += __shfl_xor_sync(0xffffffffu, c1, o);
            c2 += __shfl_xor_sync(0xffffffffu, c2, o);
            c3 += __shfl_xor_sync(0xffffffffu, c3, o);
        }
        if (lane == 0) {
            float th = ori[g * 2], ph = ori[g * 2 + 1];
            float sth = sinf(th), cth = cosf(th), sph = sinf(ph), cph = cosf(ph);
            float qx = sth * cph, qy = sth * sph, qz = cth;
            out[g] = c0 + SQRT3F * (c1 * qy + c2 * qz + c3 * qx);
        }
    }
}

// ---------------------------------------------------------------------------
extern "C" void kernel_launch(void* const* d_in, const int* in_sizes, int n_in,
                              void* d_out, int out_size)
{
    const float* pos     = (const float*)d_in[0];
    const float* x       = (const float*)d_in[1];
    const float* ori     = (const float*)d_in[2];
    const float* W_embed = (const float*)d_in[3];
    const float* W_tp    = (const float*)d_in[4];
    const float* W_fc1   = (const float*)d_in[5];
    const float* W_fc2   = (const float*)d_in[6];
    const float* W_dec   = (const float*)d_in[7];
    const int*   esrc    = (const int*)d_in[8];
    const int*   edst    = (const int*)d_in[9];
    const int*   batch   = (const int*)d_in[10];
    int N = in_sizes[10];
    int E = in_sizes[8];
    int G = in_sizes[2] / 2;
    float* out = (float*)d_out;

    void *degp, *hA, *hB, *tabp;
    cudaGetSymbolAddress(&degp, g_deg);
    cudaGetSymbolAddress(&hA, g_hA);
    cudaGetSymbolAddress(&hB, g_hB);
    cudaGetSymbolAddress(&tabp, g_tab);
    const float* tab = (const float*)tabp;

    cudaMemsetAsync(degp, 0, (size_t)N * sizeof(int));
    table_kernel<<<(3 * (TBINS + 1) + 255) / 256, 256>>>(W_fc1, W_fc2);
    pre_kernel<<<(E + 255) / 256, 256>>>(pos, esrc, edst, E);
    scan_kernel<<<1, 1024>>>(N);
    fill_kernel<<<(E + 255) / 256, 256>>>(edst, E);
    sort_kernel<<<(N + 255) / 256, 256>>>(N);
    pack_kernel<<<(E + 255) / 256, 256>>>(esrc, N, E);
    embed_kernel<<<(N * 32 + 255) / 256, 256>>>(x, W_embed, N);

    layer_kernel<<<1184, 256>>>((const float*)hA, (float*)hB, W_tp + 0 * 4096, tab + 0 * (TBINS + 1), N);
    layer_kernel<<<1184, 256>>>((const float*)hB, (float*)hA, W_tp + 1 * 4096, tab + 1 * (TBINS + 1), N);
    layer_kernel<<<1184, 256>>>((const float*)hA, (float*)hB, W_tp + 2 * 4096, tab + 2 * (TBINS + 1), N);

    pool_kernel<<<G, 256>>>((const float*)hB, ori, W_dec, batch, out, N);
}